// round 1
// baseline (speedup 1.0000x reference)
#include <cuda_runtime.h>
#include <cuda_bf16.h>
#include <math.h>

// Problem constants
#define SEQ  4096
#define DIM  1024
#define NH   16
#define HD   64

// ---------------- scratch (device globals; no allocation allowed) ----------
__device__ float g_Q[NH * SEQ * HD];    // [h][s][hd]
__device__ float g_K[NH * SEQ * HD];
__device__ float g_V[NH * SEQ * HD];
__device__ float g_ctx[SEQ * DIM];      // [s][d]

// ================= SGEMM: Y[m][n] = sum_k A[m][k] * W[n][k] ================
// BM=BN=128, BK=16, 256 threads, 8x8 per thread micro-tile.
#define GBM 128
#define GBN 128
#define GBK 16
#define GPITCH 132   // 128 + 4 pad; 132*4B = 528B, multiple of 16 -> float4 ok

__global__ __launch_bounds__(256) void proj_qkv_kernel(
    const float* __restrict__ x,
    const float* __restrict__ Wq,
    const float* __restrict__ Wk,
    const float* __restrict__ Wv)
{
    __shared__ float As[GBK][GPITCH];
    __shared__ float Bs[GBK][GPITCH];

    const int tid = threadIdx.x;
    const int tx = tid & 15;       // 0..15
    const int ty = tid >> 4;       // 0..15
    const int m0 = blockIdx.y * GBM;
    const int n0 = blockIdx.x * GBN;

    const float* W   = (blockIdx.z == 0) ? Wq : (blockIdx.z == 1) ? Wk : Wv;
    float*       dst = (blockIdx.z == 0) ? g_Q : (blockIdx.z == 1) ? g_K : g_V;

    const int lr = tid >> 2;          // 0..63
    const int lc = (tid & 3) << 2;    // 0,4,8,12

    float acc[8][8];
#pragma unroll
    for (int i = 0; i < 8; i++)
#pragma unroll
        for (int j = 0; j < 8; j++) acc[i][j] = 0.f;

    for (int k0 = 0; k0 < DIM; k0 += GBK) {
        const float4 a0 = *(const float4*)&x[(size_t)(m0 + lr)      * DIM + k0 + lc];
        const float4 a1 = *(const float4*)&x[(size_t)(m0 + lr + 64) * DIM + k0 + lc];
        const float4 b0 = *(const float4*)&W[(size_t)(n0 + lr)      * DIM + k0 + lc];
        const float4 b1 = *(const float4*)&W[(size_t)(n0 + lr + 64) * DIM + k0 + lc];
        __syncthreads();
        As[lc + 0][lr] = a0.x; As[lc + 1][lr] = a0.y; As[lc + 2][lr] = a0.z; As[lc + 3][lr] = a0.w;
        As[lc + 0][lr + 64] = a1.x; As[lc + 1][lr + 64] = a1.y; As[lc + 2][lr + 64] = a1.z; As[lc + 3][lr + 64] = a1.w;
        Bs[lc + 0][lr] = b0.x; Bs[lc + 1][lr] = b0.y; Bs[lc + 2][lr] = b0.z; Bs[lc + 3][lr] = b0.w;
        Bs[lc + 0][lr + 64] = b1.x; Bs[lc + 1][lr + 64] = b1.y; Bs[lc + 2][lr + 64] = b1.z; Bs[lc + 3][lr + 64] = b1.w;
        __syncthreads();

#pragma unroll
        for (int kk = 0; kk < GBK; kk++) {
            const float4 va0 = *(const float4*)&As[kk][ty * 4];
            const float4 va1 = *(const float4*)&As[kk][64 + ty * 4];
            const float4 vb0 = *(const float4*)&Bs[kk][tx * 4];
            const float4 vb1 = *(const float4*)&Bs[kk][64 + tx * 4];
            const float a[8] = {va0.x, va0.y, va0.z, va0.w, va1.x, va1.y, va1.z, va1.w};
            const float b[8] = {vb0.x, vb0.y, vb0.z, vb0.w, vb1.x, vb1.y, vb1.z, vb1.w};
#pragma unroll
            for (int i = 0; i < 8; i++)
#pragma unroll
                for (int j = 0; j < 8; j++) acc[i][j] += a[i] * b[j];
        }
    }

    // epilogue: scatter into [h][s][hd]
#pragma unroll
    for (int i = 0; i < 8; i++) {
        const int row = m0 + ((i < 4) ? (ty * 4 + i) : (64 + ty * 4 + i - 4));
#pragma unroll
        for (int j = 0; j < 8; j++) {
            const int col = n0 + ((j < 4) ? (tx * 4 + j) : (64 + tx * 4 + j - 4));
            const int h = col >> 6, hd = col & 63;
            dst[((size_t)h * SEQ + row) * HD + hd] = acc[i][j];
        }
    }
}

__global__ __launch_bounds__(256) void out_proj_kernel(
    const float* __restrict__ Wo,
    const float* __restrict__ bo,
    float* __restrict__ out)
{
    __shared__ float As[GBK][GPITCH];
    __shared__ float Bs[GBK][GPITCH];

    const int tid = threadIdx.x;
    const int tx = tid & 15;
    const int ty = tid >> 4;
    const int m0 = blockIdx.y * GBM;
    const int n0 = blockIdx.x * GBN;

    const int lr = tid >> 2;
    const int lc = (tid & 3) << 2;

    float acc[8][8];
#pragma unroll
    for (int i = 0; i < 8; i++)
#pragma unroll
        for (int j = 0; j < 8; j++) acc[i][j] = 0.f;

    for (int k0 = 0; k0 < DIM; k0 += GBK) {
        const float4 a0 = *(const float4*)&g_ctx[(size_t)(m0 + lr)      * DIM + k0 + lc];
        const float4 a1 = *(const float4*)&g_ctx[(size_t)(m0 + lr + 64) * DIM + k0 + lc];
        const float4 b0 = *(const float4*)&Wo[(size_t)(n0 + lr)      * DIM + k0 + lc];
        const float4 b1 = *(const float4*)&Wo[(size_t)(n0 + lr + 64) * DIM + k0 + lc];
        __syncthreads();
        As[lc + 0][lr] = a0.x; As[lc + 1][lr] = a0.y; As[lc + 2][lr] = a0.z; As[lc + 3][lr] = a0.w;
        As[lc + 0][lr + 64] = a1.x; As[lc + 1][lr + 64] = a1.y; As[lc + 2][lr + 64] = a1.z; As[lc + 3][lr + 64] = a1.w;
        Bs[lc + 0][lr] = b0.x; Bs[lc + 1][lr] = b0.y; Bs[lc + 2][lr] = b0.z; Bs[lc + 3][lr] = b0.w;
        Bs[lc + 0][lr + 64] = b1.x; Bs[lc + 1][lr + 64] = b1.y; Bs[lc + 2][lr + 64] = b1.z; Bs[lc + 3][lr + 64] = b1.w;
        __syncthreads();

#pragma unroll
        for (int kk = 0; kk < GBK; kk++) {
            const float4 va0 = *(const float4*)&As[kk][ty * 4];
            const float4 va1 = *(const float4*)&As[kk][64 + ty * 4];
            const float4 vb0 = *(const float4*)&Bs[kk][tx * 4];
            const float4 vb1 = *(const float4*)&Bs[kk][64 + tx * 4];
            const float a[8] = {va0.x, va0.y, va0.z, va0.w, va1.x, va1.y, va1.z, va1.w};
            const float b[8] = {vb0.x, vb0.y, vb0.z, vb0.w, vb1.x, vb1.y, vb1.z, vb1.w};
#pragma unroll
            for (int i = 0; i < 8; i++)
#pragma unroll
                for (int j = 0; j < 8; j++) acc[i][j] += a[i] * b[j];
        }
    }

#pragma unroll
    for (int i = 0; i < 8; i++) {
        const int row = m0 + ((i < 4) ? (ty * 4 + i) : (64 + ty * 4 + i - 4));
#pragma unroll
        for (int j = 0; j < 8; j++) {
            const int col = n0 + ((j < 4) ? (tx * 4 + j) : (64 + tx * 4 + j - 4));
            out[(size_t)row * DIM + col] = acc[i][j] + bo[col];
        }
    }
}

// ====================== Flash attention (causal, fp32) =====================
// BM=128 q-rows per CTA, BN=64 k-cols per iteration. 256 threads (16x16),
// per-thread micro-tile: 8 rows x 4 cols. Online softmax with per-row m/l.
#define AT_BM 128
#define AT_BN 64
#define PT_PITCH 129   // odd pitch: conflict-free column reads in softmax pass

// smem floats: Qt[64][128] + Pt[64][129] + Kt[64][64] + Vs[64][64] + 3*128
#define ATTN_SMEM_FLOATS (64*128 + 64*PT_PITCH + 64*64 + 64*64 + 3*128)
#define ATTN_SMEM_BYTES  (ATTN_SMEM_FLOATS * 4)

__global__ __launch_bounds__(256) void attn_kernel()
{
    extern __shared__ float sm[];
    float* Qt  = sm;                       // [hd=64][row=128], Qt[c][r] = Q[r][c]
    float* Pt  = Qt + 64 * 128;            // [col=64][row=128+pad]
    float* Kt  = Pt + 64 * PT_PITCH;       // [hd=64][col=64],  Kt[c][n] = K[n][c]
    float* Vs  = Kt + 64 * 64;             // [n=64][hd=64] natural
    float* m_s = Vs + 64 * 64;             // [128]
    float* l_s = m_s + 128;                // [128]
    float* al_s = l_s + 128;               // [128]

    const int tid  = threadIdx.x;
    const int tx   = tid & 15;
    const int ty   = tid >> 4;
    const int wid  = tid >> 5;
    const int lane = tid & 31;

    const int qb = (gridDim.x - 1) - blockIdx.x;  // reversed: big blocks first
    const int h  = blockIdx.y;

    const float* Qg = g_Q + (size_t)h * SEQ * HD;
    const float* Kg = g_K + (size_t)h * SEQ * HD;
    const float* Vg = g_V + (size_t)h * SEQ * HD;

    // Load Q tile transposed: Qt[c][r]
    for (int idx = tid; idx < 128 * 16; idx += 256) {
        const int r  = idx & 127;
        const int c4 = idx >> 7;            // 0..15
        const float4 v = *(const float4*)&Qg[(size_t)(qb * AT_BM + r) * HD + c4 * 4];
        Qt[(c4 * 4 + 0) * 128 + r] = v.x;
        Qt[(c4 * 4 + 1) * 128 + r] = v.y;
        Qt[(c4 * 4 + 2) * 128 + r] = v.z;
        Qt[(c4 * 4 + 3) * 128 + r] = v.w;
    }
    if (tid < 128) { m_s[tid] = -INFINITY; l_s[tid] = 0.f; }

    float o_[8][4];
#pragma unroll
    for (int i = 0; i < 8; i++)
#pragma unroll
        for (int j = 0; j < 4; j++) o_[i][j] = 0.f;

    const int jmax = 2 * qb + 1;  // causal: k-block j covers cols [j*64, j*64+63]

    for (int j = 0; j <= jmax; j++) {
        __syncthreads();  // protect Kt/Vs/Pt from previous iteration readers

        // Load K transposed (Kt[c][n]) and V natural (Vs[n][c])
        for (int idx = tid; idx < 64 * 16; idx += 256) {
            // K: row-fast mapping -> conflict-free transposed smem stores
            const int rK  = idx & 63;
            const int cK4 = idx >> 6;
            const float4 kv = *(const float4*)&Kg[(size_t)(j * AT_BN + rK) * HD + cK4 * 4];
            Kt[(cK4 * 4 + 0) * 64 + rK] = kv.x;
            Kt[(cK4 * 4 + 1) * 64 + rK] = kv.y;
            Kt[(cK4 * 4 + 2) * 64 + rK] = kv.z;
            Kt[(cK4 * 4 + 3) * 64 + rK] = kv.w;
            // V: col-fast mapping -> coalesced global, conflict-free smem
            const int rV  = idx >> 4;
            const int cV4 = idx & 15;
            const float4 vv = *(const float4*)&Vg[(size_t)(j * AT_BN + rV) * HD + cV4 * 4];
            *(float4*)&Vs[rV * 64 + cV4 * 4] = vv;
        }
        __syncthreads();

        // S = Q @ K^T for this tile (regs)
        float s_[8][4];
#pragma unroll
        for (int i = 0; i < 8; i++)
#pragma unroll
            for (int jj = 0; jj < 4; jj++) s_[i][jj] = 0.f;

#pragma unroll 16
        for (int kk = 0; kk < 64; kk++) {
            const float4 b = *(const float4*)&Kt[kk * 64 + (tx << 2)];
#pragma unroll
            for (int ri = 0; ri < 8; ri++) {
                const float a = Qt[kk * 128 + (ty << 3) + ri];
                s_[ri][0] += a * b.x;
                s_[ri][1] += a * b.y;
                s_[ri][2] += a * b.z;
                s_[ri][3] += a * b.w;
            }
        }

        // scale + causal mask + stage into Pt[col][row]
        const int  q0 = qb * AT_BM + (ty << 3);
        const int  k0 = j * AT_BN + (tx << 2);
        const bool need_mask = (j >= 2 * qb);
#pragma unroll
        for (int ri = 0; ri < 8; ri++) {
#pragma unroll
            for (int jj = 0; jj < 4; jj++) {
                float v = s_[ri][jj] * 0.125f;  // 1/sqrt(64)
                if (need_mask && (k0 + jj > q0 + ri)) v = -1e30f;
                Pt[(k0 - j * AT_BN + jj) * PT_PITCH + (ty << 3) + ri] = v;
            }
        }
        __syncthreads();

        // Online softmax: warp w owns rows [w*16, w*16+16)
        for (int rr = 0; rr < 16; rr++) {
            const int r = wid * 16 + rr;
            float v0 = Pt[lane * PT_PITCH + r];
            float v1 = Pt[(lane + 32) * PT_PITCH + r];
            float mx = fmaxf(v0, v1);
#pragma unroll
            for (int off = 16; off; off >>= 1)
                mx = fmaxf(mx, __shfl_xor_sync(0xffffffffu, mx, off));
            const float mold = m_s[r];
            const float mnew = fmaxf(mold, mx);
            const float p0 = __expf(v0 - mnew);
            const float p1 = __expf(v1 - mnew);
            Pt[lane * PT_PITCH + r] = p0;
            Pt[(lane + 32) * PT_PITCH + r] = p1;
            float sum = p0 + p1;
#pragma unroll
            for (int off = 16; off; off >>= 1)
                sum += __shfl_xor_sync(0xffffffffu, sum, off);
            if (lane == 0) {
                const float al = __expf(mold - mnew);
                al_s[r] = al;
                l_s[r] = l_s[r] * al + sum;
                m_s[r] = mnew;
            }
        }
        __syncthreads();

        // O = O*alpha + P @ V
#pragma unroll
        for (int ri = 0; ri < 8; ri++) {
            const float al = al_s[(ty << 3) + ri];
#pragma unroll
            for (int jj = 0; jj < 4; jj++) o_[ri][jj] *= al;
        }
#pragma unroll 16
        for (int n = 0; n < 64; n++) {
            const float4 v = *(const float4*)&Vs[n * 64 + (tx << 2)];
#pragma unroll
            for (int ri = 0; ri < 8; ri++) {
                const float p = Pt[n * PT_PITCH + (ty << 3) + ri];
                o_[ri][0] += p * v.x;
                o_[ri][1] += p * v.y;
                o_[ri][2] += p * v.z;
                o_[ri][3] += p * v.w;
            }
        }
    }

    // epilogue: ctx[s][h*64 + hd] = O / l
#pragma unroll
    for (int ri = 0; ri < 8; ri++) {
        const int row = (ty << 3) + ri;
        const float inv = 1.f / l_s[row];
        float4 v;
        v.x = o_[ri][0] * inv;
        v.y = o_[ri][1] * inv;
        v.z = o_[ri][2] * inv;
        v.w = o_[ri][3] * inv;
        *(float4*)&g_ctx[(size_t)(qb * AT_BM + row) * DIM + h * HD + (tx << 2)] = v;
    }
}

// ================================ launch ===================================
extern "C" void kernel_launch(void* const* d_in, const int* in_sizes, int n_in,
                              void* d_out, int out_size)
{
    (void)in_sizes; (void)n_in; (void)out_size;
    const float* x  = (const float*)d_in[0];
    const float* Wq = (const float*)d_in[1];
    const float* Wk = (const float*)d_in[2];
    const float* Wv = (const float*)d_in[3];
    const float* Wo = (const float*)d_in[4];
    const float* bo = (const float*)d_in[5];
    float* out = (float*)d_out;

    // Q/K/V projections: M=4096, N=1024, z = which weight
    proj_qkv_kernel<<<dim3(DIM / GBN, SEQ / GBM, 3), 256>>>(x, Wq, Wk, Wv);

    // Flash attention: 32 q-blocks x 16 heads
    cudaFuncSetAttribute(attn_kernel, cudaFuncAttributeMaxDynamicSharedMemorySize,
                         ATTN_SMEM_BYTES);
    attn_kernel<<<dim3(SEQ / AT_BM, NH), 256, ATTN_SMEM_BYTES>>>();

    // Output projection + bias
    out_proj_kernel<<<dim3(DIM / GBN, SEQ / GBM), 256>>>(Wo, bo, out);
}

// round 6
// speedup vs baseline: 6.7067x; 6.7067x over previous
#include <cuda_runtime.h>
#include <cuda_fp16.h>
#include <stdint.h>

#define SEQ 4096
#define DIM 1024
#define NH  16
#define HD  64

// ---------------- fp16 scratch (device globals; no allocation allowed) -----
__device__ __align__(128) __half g_xh [SEQ * DIM];
__device__ __align__(128) __half g_wqh[DIM * DIM];
__device__ __align__(128) __half g_wkh[DIM * DIM];
__device__ __align__(128) __half g_wvh[DIM * DIM];
__device__ __align__(128) __half g_woh[DIM * DIM];
__device__ __align__(128) __half g_qh [NH * SEQ * HD];   // [h][s][hd]
__device__ __align__(128) __half g_kh [NH * SEQ * HD];   // [h][s][hd]
__device__ __align__(128) __half g_vh [NH * SEQ * HD];   // [h][s][hd]
__device__ __align__(128) __half g_ctxh[SEQ * DIM];      // [s][d]

// ========================= PTX helpers =====================================
__device__ __forceinline__ uint32_t smem_u32(const void* p) {
    uint32_t a;
    asm("{ .reg .u64 t; cvta.to.shared.u64 t, %1; cvt.u32.u64 %0, t; }"
        : "=r"(a) : "l"(p));
    return a;
}
__device__ __forceinline__ void ldsm4(uint32_t* r, uint32_t a) {
    asm volatile("ldmatrix.sync.aligned.m8n8.x4.shared.b16 {%0,%1,%2,%3}, [%4];"
                 : "=r"(r[0]), "=r"(r[1]), "=r"(r[2]), "=r"(r[3]) : "r"(a));
}
__device__ __forceinline__ void ldsm4t(uint32_t* r, uint32_t a) {
    asm volatile("ldmatrix.sync.aligned.m8n8.x4.trans.shared.b16 {%0,%1,%2,%3}, [%4];"
                 : "=r"(r[0]), "=r"(r[1]), "=r"(r[2]), "=r"(r[3]) : "r"(a));
}
__device__ __forceinline__ void mma16816(float* d, const uint32_t* a,
                                         uint32_t b0, uint32_t b1) {
    asm volatile(
        "mma.sync.aligned.m16n8k16.row.col.f32.f16.f16.f32 "
        "{%0,%1,%2,%3}, {%4,%5,%6,%7}, {%8,%9}, {%0,%1,%2,%3};"
        : "+f"(d[0]), "+f"(d[1]), "+f"(d[2]), "+f"(d[3])
        : "r"(a[0]), "r"(a[1]), "r"(a[2]), "r"(a[3]), "r"(b0), "r"(b1));
}
#define CP16(sa, gp) \
    asm volatile("cp.async.cg.shared.global [%0], [%1], 16;" :: "r"(sa), "l"(gp))
#define CP_COMMIT() asm volatile("cp.async.commit_group;" ::: "memory")
#define CP_WAIT1()  asm volatile("cp.async.wait_group 1;" ::: "memory")
#define CP_WAIT0()  asm volatile("cp.async.wait_group 0;" ::: "memory")

__device__ __forceinline__ uint32_t pack_h2(float a, float b) {
    __half2 h = __floats2half2_rn(a, b);
    return *(uint32_t*)&h;
}

// =========================== fp32 -> fp16 convert ==========================
__global__ __launch_bounds__(256) void convert_kernel(
    const float* __restrict__ x,  const float* __restrict__ wq,
    const float* __restrict__ wk, const float* __restrict__ wv,
    const float* __restrict__ wo)
{
    const int i = blockIdx.x * 256 + threadIdx.x;   // float4 index
    const int XN = SEQ * DIM / 4, WN = DIM * DIM / 4;
    const float* src; __half* dst; int off;
    if (i < XN) { src = x; dst = g_xh; off = i; }
    else {
        int j = i - XN; int w = j / WN; off = j - w * WN;
        src = (w == 0) ? wq : (w == 1) ? wk : (w == 2) ? wv : wo;
        dst = (w == 0) ? g_wqh : (w == 1) ? g_wkh : (w == 2) ? g_wvh : g_woh;
    }
    float4 v = ((const float4*)src)[off];
    uint2 u;
    u.x = pack_h2(v.x, v.y);
    u.y = pack_h2(v.z, v.w);
    ((uint2*)dst)[off] = u;
}

// ================== HMMA GEMM: Y[m][n] = sum_k A[m][k] B[n][k] =============
// BM=BN=128, BK=32, 256 threads = 8 warps (4m x 2n), 64x32 per-warp tile.
#define BK 32
#define AP 40   // smem pitch in halfs; r*80B distinct mod 128 -> ldmatrix OK

struct GemmSmem {
    __half A[2][128 * AP];
    __half B[2][128 * AP];
};

// loads one BK stage via cp.async
__device__ __forceinline__ void hgemm_load(
    GemmSmem* sm, const __half* __restrict__ Ag, const __half* __restrict__ Bg,
    int c, int tid)
{
    const int stage = c & 1;
    const uint32_t aB = smem_u32(sm->A[stage]);
    const uint32_t bB = smem_u32(sm->B[stage]);
#pragma unroll
    for (int i = 0; i < 2; i++) {
        int idx = i * 256 + tid;          // 0..511 chunks of 16B
        int r = idx >> 2, q = idx & 3;    // row, 16B-chunk within 64B row
        CP16(aB + r * (AP * 2) + q * 16, Ag + (size_t)r * DIM + c * BK + q * 8);
        CP16(bB + r * (AP * 2) + q * 16, Bg + (size_t)r * DIM + c * BK + q * 8);
    }
}

__device__ __forceinline__ void hgemm_mainloop(
    GemmSmem* sm, const __half* __restrict__ Ag, const __half* __restrict__ Bg,
    float acc[2][8][4])
{
    const int tid = threadIdx.x;
    const int l = tid & 31, wid = tid >> 5;
    const int wm = wid >> 1, wn = wid & 1;

#pragma unroll
    for (int mi = 0; mi < 2; mi++)
#pragma unroll
        for (int f = 0; f < 8; f++)
#pragma unroll
            for (int e = 0; e < 4; e++) acc[mi][f][e] = 0.f;

    hgemm_load(sm, Ag, Bg, 0, tid);
    CP_COMMIT();

    // per-lane ldmatrix offsets (halfs)
    const int aRow = wm * 32 + (l & 15);
    const int aCol = (l >> 4) << 3;
    const int bRow = wn * 64 + (l & 7) + ((l >> 4) << 3);
    const int bCol = ((l >> 3) & 1) << 3;

    for (int c = 0; c < DIM / BK; c++) {
        if (c + 1 < DIM / BK) {
            hgemm_load(sm, Ag, Bg, c + 1, tid);
            CP_COMMIT();
            CP_WAIT1();
        } else {
            CP_WAIT0();
        }
        __syncthreads();

        const int stage = c & 1;
        const uint32_t aS = smem_u32(sm->A[stage]);
        const uint32_t bS = smem_u32(sm->B[stage]);
#pragma unroll
        for (int ks = 0; ks < 2; ks++) {
            const int k0 = ks * 16;
            uint32_t af[2][4];
#pragma unroll
            for (int mi = 0; mi < 2; mi++)
                ldsm4(af[mi], aS + ((aRow + mi * 16) * AP + k0 + aCol) * 2);
            uint32_t bf[4][4];
#pragma unroll
            for (int g = 0; g < 4; g++)
                ldsm4(bf[g], bS + ((bRow + g * 16) * AP + k0 + bCol) * 2);
#pragma unroll
            for (int mi = 0; mi < 2; mi++)
#pragma unroll
                for (int f = 0; f < 8; f++) {
                    const int g = f >> 1, o = (f & 1) * 2;
                    mma16816(acc[mi][f], af[mi], bf[g][o], bf[g][o + 1]);
                }
        }
        __syncthreads();
    }
}

__global__ __launch_bounds__(256, 2) void gemm_proj_kernel()
{
    __shared__ GemmSmem sm;
    const int tid = threadIdx.x;
    const int l = tid & 31, wid = tid >> 5;
    const int wm = wid >> 1, wn = wid & 1;
    const int m0 = blockIdx.y * 128, n0 = blockIdx.x * 128;
    const int z = blockIdx.z;
    const __half* B = (z == 0) ? g_wqh : (z == 1) ? g_wkh : g_wvh;
    __half* dst = (z == 0) ? g_qh : (z == 1) ? g_kh : g_vh;

    float acc[2][8][4];
    hgemm_mainloop(&sm, g_xh + (size_t)m0 * DIM, B + (size_t)n0 * DIM, acc);

#pragma unroll
    for (int mi = 0; mi < 2; mi++)
#pragma unroll
        for (int f = 0; f < 8; f++) {
            const int r  = m0 + wm * 32 + mi * 16 + (l >> 2);
            const int cc = n0 + wn * 64 + f * 8 + ((l & 3) << 1);
            const int h = cc >> 6, hd = cc & 63;
            const size_t base = ((size_t)h * SEQ + r) * HD + hd;
            *(__half2*)&dst[base] = __floats2half2_rn(acc[mi][f][0], acc[mi][f][1]);
            *(__half2*)&dst[base + 8 * HD] =
                __floats2half2_rn(acc[mi][f][2], acc[mi][f][3]);
        }
}

__global__ __launch_bounds__(256, 2) void out_proj_kernel(
    const float* __restrict__ bo, float* __restrict__ out)
{
    __shared__ GemmSmem sm;
    const int tid = threadIdx.x;
    const int l = tid & 31, wid = tid >> 5;
    const int wm = wid >> 1, wn = wid & 1;
    const int m0 = blockIdx.y * 128, n0 = blockIdx.x * 128;

    float acc[2][8][4];
    hgemm_mainloop(&sm, g_ctxh + (size_t)m0 * DIM, g_woh + (size_t)n0 * DIM, acc);

#pragma unroll
    for (int mi = 0; mi < 2; mi++)
#pragma unroll
        for (int f = 0; f < 8; f++) {
            const int r  = m0 + wm * 32 + mi * 16 + (l >> 2);
            const int cc = n0 + wn * 64 + f * 8 + ((l & 3) << 1);
            const float2 b2 = *(const float2*)&bo[cc];
            float2 v0, v1;
            v0.x = acc[mi][f][0] + b2.x; v0.y = acc[mi][f][1] + b2.y;
            v1.x = acc[mi][f][2] + b2.x; v1.y = acc[mi][f][3] + b2.y;
            *(float2*)&out[(size_t)r * DIM + cc] = v0;
            *(float2*)&out[(size_t)(r + 8) * DIM + cc] = v1;
        }
}

// ================== HMMA flash attention (causal, fp16) ====================
// 256 threads = 8 warps; warp w owns q-rows [w*16, w*16+16). BN=64 per iter.
#define QP 72   // smem pitch (halfs) for 64-wide tiles: r*144B distinct mod 128

__global__ __launch_bounds__(256, 2) void attn_kernel()
{
    __shared__ __half sQ[128 * QP];
    __shared__ __half sK[64 * QP];
    __shared__ __half sV[64 * QP];

    const int tid = threadIdx.x;
    const int l = tid & 31, wid = tid >> 5;
    const int qb = (gridDim.x - 1) - blockIdx.x;   // big blocks first
    const int h = blockIdx.y;

    const __half* Qg = g_qh + ((size_t)h * SEQ + (size_t)qb * 128) * HD;
    const __half* Kg = g_kh + (size_t)h * SEQ * HD;
    const __half* Vg = g_vh + (size_t)h * SEQ * HD;

    const uint32_t qB = smem_u32(sQ), kB = smem_u32(sK), vB = smem_u32(sV);

    // load Q tile [128][64] -> pitch-72 smem
#pragma unroll
    for (int i = 0; i < 4; i++) {
        int idx = i * 256 + tid;          // 0..1023 chunks of 16B
        int r = idx >> 3, q = idx & 7;
        *(uint4*)(sQ + r * QP + q * 8) = *(const uint4*)(Qg + (size_t)r * HD + q * 8);
    }
    __syncthreads();

    // Q fragments (A operand), rows warp*16..+15, k=64 in 4 k16 steps
    uint32_t qf[4][4];
    {
        const int row = wid * 16 + (l & 15);
        const int col = (l >> 4) << 3;
#pragma unroll
        for (int ks = 0; ks < 4; ks++)
            ldsm4(qf[ks], qB + (row * QP + ks * 16 + col) * 2);
    }

    const int r0g = qb * 128 + wid * 16 + (l >> 2);   // global q row (part 0)
    const int r1g = r0g + 8;                          // part 1
    float m0r = -1e30f, m1r = -1e30f, l0r = 0.f, l1r = 0.f;
    float oacc[8][4];
#pragma unroll
    for (int f = 0; f < 8; f++)
#pragma unroll
        for (int e = 0; e < 4; e++) oacc[f][e] = 0.f;

    // lane offsets for K (non-trans B frags) and V (trans B frags)
    const int kRow = (l & 7) + ((l >> 4) << 3);
    const int kCol = ((l >> 3) & 1) << 3;
    const int vRow = (l & 7) + (((l >> 3) & 1) << 3);
    const int vCol = (l >> 4) << 3;

    const int jmax = 2 * qb + 1;
    for (int j = 0; j <= jmax; j++) {
        // load K, V tiles [64][64]
#pragma unroll
        for (int i = 0; i < 2; i++) {
            int idx = i * 256 + tid;      // 0..511
            int r = idx >> 3, q = idx & 7;
            *(uint4*)(sK + r * QP + q * 8) =
                *(const uint4*)(Kg + ((size_t)j * 64 + r) * HD + q * 8);
            *(uint4*)(sV + r * QP + q * 8) =
                *(const uint4*)(Vg + ((size_t)j * 64 + r) * HD + q * 8);
        }
        __syncthreads();

        // ---- S = Q @ K^T : 16x64 per warp ----
        float sacc[8][4];
#pragma unroll
        for (int f = 0; f < 8; f++)
#pragma unroll
            for (int e = 0; e < 4; e++) sacc[f][e] = 0.f;

#pragma unroll
        for (int ks = 0; ks < 4; ks++) {
            uint32_t bf[4][4];
#pragma unroll
            for (int g = 0; g < 4; g++)
                ldsm4(bf[g], kB + ((g * 16 + kRow) * QP + ks * 16 + kCol) * 2);
#pragma unroll
            for (int f = 0; f < 8; f++) {
                const int g = f >> 1, o = (f & 1) * 2;
                mma16816(sacc[f], qf[ks], bf[g][o], bf[g][o + 1]);
            }
        }

        // ---- online softmax (thread-local rows r0g, r1g) ----
        const bool edge = (j >= 2 * qb);
        float mx0 = m0r, mx1 = m1r;
#pragma unroll
        for (int f = 0; f < 8; f++) {
            const int cb = j * 64 + f * 8 + ((l & 3) << 1);
            float v0 = sacc[f][0] * 0.125f, v1 = sacc[f][1] * 0.125f;
            float v2 = sacc[f][2] * 0.125f, v3 = sacc[f][3] * 0.125f;
            if (edge) {
                if (cb     > r0g) v0 = -1e30f;
                if (cb + 1 > r0g) v1 = -1e30f;
                if (cb     > r1g) v2 = -1e30f;
                if (cb + 1 > r1g) v3 = -1e30f;
            }
            sacc[f][0] = v0; sacc[f][1] = v1; sacc[f][2] = v2; sacc[f][3] = v3;
            mx0 = fmaxf(mx0, fmaxf(v0, v1));
            mx1 = fmaxf(mx1, fmaxf(v2, v3));
        }
        mx0 = fmaxf(mx0, __shfl_xor_sync(0xffffffffu, mx0, 1));
        mx0 = fmaxf(mx0, __shfl_xor_sync(0xffffffffu, mx0, 2));
        mx1 = fmaxf(mx1, __shfl_xor_sync(0xffffffffu, mx1, 1));
        mx1 = fmaxf(mx1, __shfl_xor_sync(0xffffffffu, mx1, 2));

        const float al0 = __expf(m0r - mx0);
        const float al1 = __expf(m1r - mx1);
        m0r = mx0; m1r = mx1;

        float s0 = 0.f, s1 = 0.f;
        uint32_t pl[8], ph[8];
#pragma unroll
        for (int f = 0; f < 8; f++) {
            const float p0 = __expf(sacc[f][0] - mx0);
            const float p1 = __expf(sacc[f][1] - mx0);
            const float p2 = __expf(sacc[f][2] - mx1);
            const float p3 = __expf(sacc[f][3] - mx1);
            s0 += p0 + p1; s1 += p2 + p3;
            pl[f] = pack_h2(p0, p1);
            ph[f] = pack_h2(p2, p3);
        }
        s0 += __shfl_xor_sync(0xffffffffu, s0, 1);
        s0 += __shfl_xor_sync(0xffffffffu, s0, 2);
        s1 += __shfl_xor_sync(0xffffffffu, s1, 1);
        s1 += __shfl_xor_sync(0xffffffffu, s1, 2);
        l0r = l0r * al0 + s0;
        l1r = l1r * al1 + s1;

        // ---- O = O*alpha + P @ V ----
#pragma unroll
        for (int f = 0; f < 8; f++) {
            oacc[f][0] *= al0; oacc[f][1] *= al0;
            oacc[f][2] *= al1; oacc[f][3] *= al1;
        }
#pragma unroll
        for (int ks = 0; ks < 4; ks++) {
            uint32_t a[4] = {pl[2 * ks], ph[2 * ks], pl[2 * ks + 1], ph[2 * ks + 1]};
            uint32_t bv[4][4];
#pragma unroll
            for (int g = 0; g < 4; g++)
                ldsm4t(bv[g], vB + ((ks * 16 + vRow) * QP + g * 16 + vCol) * 2);
#pragma unroll
            for (int f = 0; f < 8; f++) {
                const int g = f >> 1, o = (f & 1) * 2;
                mma16816(oacc[f], a, bv[g][o], bv[g][o + 1]);
            }
        }
        __syncthreads();   // all warps done reading sK/sV before next overwrite
    }

    // epilogue: ctx[row][h*64 + c] = O / l  (fp16)
    const float inv0 = 1.f / l0r, inv1 = 1.f / l1r;
#pragma unroll
    for (int f = 0; f < 8; f++) {
        const int cc = h * HD + f * 8 + ((l & 3) << 1);
        *(__half2*)&g_ctxh[(size_t)r0g * DIM + cc] =
            __floats2half2_rn(oacc[f][0] * inv0, oacc[f][1] * inv0);
        *(__half2*)&g_ctxh[(size_t)r1g * DIM + cc] =
            __floats2half2_rn(oacc[f][2] * inv1, oacc[f][3] * inv1);
    }
}

// ================================ launch ===================================
extern "C" void kernel_launch(void* const* d_in, const int* in_sizes, int n_in,
                              void* d_out, int out_size)
{
    (void)in_sizes; (void)n_in; (void)out_size;
    const float* x  = (const float*)d_in[0];
    const float* Wq = (const float*)d_in[1];
    const float* Wk = (const float*)d_in[2];
    const float* Wv = (const float*)d_in[3];
    const float* Wo = (const float*)d_in[4];
    const float* bo = (const float*)d_in[5];
    float* out = (float*)d_out;

    convert_kernel<<<8192, 256>>>(x, Wq, Wk, Wv, Wo);
    gemm_proj_kernel<<<dim3(DIM / 128, SEQ / 128, 3), 256>>>();
    attn_kernel<<<dim3(SEQ / 128, NH), 256>>>();
    out_proj_kernel<<<dim3(DIM / 128, SEQ / 128), 256>>>(bo, out);
}

// round 11
// speedup vs baseline: 7.0503x; 1.0512x over previous
#include <cuda_runtime.h>
#include <cuda_fp16.h>
#include <stdint.h>

#define SEQ 4096
#define DIM 1024
#define NH  16
#define HD  64

// ---------------- fp16 scratch (device globals; no allocation allowed) -----
__device__ __align__(128) __half g_xh [SEQ * DIM];
__device__ __align__(128) __half g_wqh[DIM * DIM];
__device__ __align__(128) __half g_wkh[DIM * DIM];
__device__ __align__(128) __half g_wvh[DIM * DIM];
__device__ __align__(128) __half g_woh[DIM * DIM];
__device__ __align__(128) __half g_qh [NH * SEQ * HD];   // [h][s][hd]
__device__ __align__(128) __half g_kh [NH * SEQ * HD];   // [h][s][hd]
__device__ __align__(128) __half g_vh [NH * SEQ * HD];   // [h][s][hd]
__device__ __align__(128) __half g_ctxh[SEQ * DIM];      // [s][d]

// ========================= PTX helpers =====================================
__device__ __forceinline__ uint32_t smem_u32(const void* p) {
    uint32_t a;
    asm("{ .reg .u64 t; cvta.to.shared.u64 t, %1; cvt.u32.u64 %0, t; }"
        : "=r"(a) : "l"(p));
    return a;
}
__device__ __forceinline__ void ldsm4(uint32_t* r, uint32_t a) {
    asm volatile("ldmatrix.sync.aligned.m8n8.x4.shared.b16 {%0,%1,%2,%3}, [%4];"
                 : "=r"(r[0]), "=r"(r[1]), "=r"(r[2]), "=r"(r[3]) : "r"(a));
}
__device__ __forceinline__ void ldsm4t(uint32_t* r, uint32_t a) {
    asm volatile("ldmatrix.sync.aligned.m8n8.x4.trans.shared.b16 {%0,%1,%2,%3}, [%4];"
                 : "=r"(r[0]), "=r"(r[1]), "=r"(r[2]), "=r"(r[3]) : "r"(a));
}
__device__ __forceinline__ void mma16816(float* d, const uint32_t* a,
                                         uint32_t b0, uint32_t b1) {
    asm volatile(
        "mma.sync.aligned.m16n8k16.row.col.f32.f16.f16.f32 "
        "{%0,%1,%2,%3}, {%4,%5,%6,%7}, {%8,%9}, {%0,%1,%2,%3};"
        : "+f"(d[0]), "+f"(d[1]), "+f"(d[2]), "+f"(d[3])
        : "r"(a[0]), "r"(a[1]), "r"(a[2]), "r"(a[3]), "r"(b0), "r"(b1));
}
#define CP16(sa, gp) \
    asm volatile("cp.async.cg.shared.global [%0], [%1], 16;" :: "r"(sa), "l"(gp))
#define CP_COMMIT()  asm volatile("cp.async.commit_group;" ::: "memory")
#define CP_WAIT_G2() asm volatile("cp.async.wait_group 2;" ::: "memory")
#define CP_WAIT_G0() asm volatile("cp.async.wait_group 0;" ::: "memory")

__device__ __forceinline__ uint32_t pack_h2(float a, float b) {
    __half2 h = __floats2half2_rn(a, b);
    return *(uint32_t*)&h;
}

// =========================== fp32 -> fp16 convert ==========================
__global__ __launch_bounds__(256) void convert_kernel(
    const float* __restrict__ x,  const float* __restrict__ wq,
    const float* __restrict__ wk, const float* __restrict__ wv,
    const float* __restrict__ wo)
{
    const int i = blockIdx.x * 256 + threadIdx.x;   // float4 index
    const int XN = SEQ * DIM / 4, WN = DIM * DIM / 4;
    const float* src; __half* dst; int off;
    if (i < XN) { src = x; dst = g_xh; off = i; }
    else {
        int j = i - XN; int w = j / WN; off = j - w * WN;
        src = (w == 0) ? wq : (w == 1) ? wk : (w == 2) ? wv : wo;
        dst = (w == 0) ? g_wqh : (w == 1) ? g_wkh : (w == 2) ? g_wvh : g_woh;
    }
    float4 v = ((const float4*)src)[off];
    uint2 u;
    u.x = pack_h2(v.x, v.y);
    u.y = pack_h2(v.z, v.w);
    ((uint2*)dst)[off] = u;
}

// ================== HMMA GEMM: Y[m][n] = sum_k A[m][k] B[n][k] =============
// BM=BN=128, BK=32, 256 threads = 8 warps (4m x 2n), 64x32 per-warp tile.
// 4-stage cp.async pipeline, single __syncthreads per K-step.
#define BK 32
#define AP 40                       // smem pitch in halfs (80B rows)
#define G_ABYTES (128 * AP * 2)     // 10240 B per stage per operand
#define G_STAGE  (2 * G_ABYTES)     // 20480 B per stage (A + B)
#define G_NSTAGE 4
#define GEMM_SMEM_TOT (G_NSTAGE * G_STAGE)   // 81920 B
#define G_NC (DIM / BK)             // 32

__device__ __forceinline__ void hgemm_load(
    char* smem, const __half* __restrict__ Ag, const __half* __restrict__ Bg,
    int c, int tid)
{
    const uint32_t base = smem_u32(smem + (c & (G_NSTAGE - 1)) * G_STAGE);
#pragma unroll
    for (int i = 0; i < 2; i++) {
        int idx = i * 256 + tid;          // 0..511 chunks of 16B
        int r = idx >> 2, q = idx & 3;    // row, 16B-chunk within 64B row
        CP16(base + r * (AP * 2) + q * 16, Ag + (size_t)r * DIM + c * BK + q * 8);
        CP16(base + G_ABYTES + r * (AP * 2) + q * 16,
             Bg + (size_t)r * DIM + c * BK + q * 8);
    }
}

__device__ __forceinline__ void hgemm_mainloop(
    char* smem, const __half* __restrict__ Ag, const __half* __restrict__ Bg,
    float acc[2][8][4])
{
    const int tid = threadIdx.x;
    const int l = tid & 31, wid = tid >> 5;
    const int wm = wid >> 1, wn = wid & 1;

#pragma unroll
    for (int mi = 0; mi < 2; mi++)
#pragma unroll
        for (int f = 0; f < 8; f++)
#pragma unroll
            for (int e = 0; e < 4; e++) acc[mi][f][e] = 0.f;

    // prologue: 3 stages in flight
#pragma unroll
    for (int s = 0; s < 3; s++) { hgemm_load(smem, Ag, Bg, s, tid); CP_COMMIT(); }

    // per-lane ldmatrix offsets (halfs)
    const int aRow = wm * 32 + (l & 15);
    const int aCol = (l >> 4) << 3;
    const int bRow = wn * 64 + (l & 7) + ((l >> 4) << 3);
    const int bCol = ((l >> 3) & 1) << 3;

    for (int c = 0; c < G_NC; c++) {
        CP_WAIT_G2();
        __syncthreads();
        if (c + 3 < G_NC) hgemm_load(smem, Ag, Bg, c + 3, tid);
        CP_COMMIT();   // unconditional: keeps wait_group accounting uniform

        const uint32_t aS = smem_u32(smem + (c & (G_NSTAGE - 1)) * G_STAGE);
        const uint32_t bS = aS + G_ABYTES;
#pragma unroll
        for (int ks = 0; ks < 2; ks++) {
            const int k0 = ks * 16;
            uint32_t af[2][4];
#pragma unroll
            for (int mi = 0; mi < 2; mi++)
                ldsm4(af[mi], aS + ((aRow + mi * 16) * AP + k0 + aCol) * 2);
            uint32_t bf[4][4];
#pragma unroll
            for (int g = 0; g < 4; g++)
                ldsm4(bf[g], bS + ((bRow + g * 16) * AP + k0 + bCol) * 2);
#pragma unroll
            for (int mi = 0; mi < 2; mi++)
#pragma unroll
                for (int f = 0; f < 8; f++) {
                    const int g = f >> 1, o = (f & 1) * 2;
                    mma16816(acc[mi][f], af[mi], bf[g][o], bf[g][o + 1]);
                }
        }
    }
}

__global__ __launch_bounds__(256, 2) void gemm_proj_kernel()
{
    extern __shared__ char smem[];
    const int tid = threadIdx.x;
    const int l = tid & 31, wid = tid >> 5;
    const int wm = wid >> 1, wn = wid & 1;
    const int m0 = blockIdx.y * 128, n0 = blockIdx.x * 128;
    const int z = blockIdx.z;
    const __half* B = (z == 0) ? g_wqh : (z == 1) ? g_wkh : g_wvh;
    __half* dst = (z == 0) ? g_qh : (z == 1) ? g_kh : g_vh;

    float acc[2][8][4];
    hgemm_mainloop(smem, g_xh + (size_t)m0 * DIM, B + (size_t)n0 * DIM, acc);

#pragma unroll
    for (int mi = 0; mi < 2; mi++)
#pragma unroll
        for (int f = 0; f < 8; f++) {
            const int r  = m0 + wm * 32 + mi * 16 + (l >> 2);
            const int cc = n0 + wn * 64 + f * 8 + ((l & 3) << 1);
            const int h = cc >> 6, hd = cc & 63;
            const size_t base = ((size_t)h * SEQ + r) * HD + hd;
            *(__half2*)&dst[base] = __floats2half2_rn(acc[mi][f][0], acc[mi][f][1]);
            *(__half2*)&dst[base + 8 * HD] =
                __floats2half2_rn(acc[mi][f][2], acc[mi][f][3]);
        }
}

__global__ __launch_bounds__(256, 2) void out_proj_kernel(
    const float* __restrict__ bo, float* __restrict__ out)
{
    extern __shared__ char smem[];
    const int tid = threadIdx.x;
    const int l = tid & 31, wid = tid >> 5;
    const int wm = wid >> 1, wn = wid & 1;
    const int m0 = blockIdx.y * 128, n0 = blockIdx.x * 128;

    float acc[2][8][4];
    hgemm_mainloop(smem, g_ctxh + (size_t)m0 * DIM, g_woh + (size_t)n0 * DIM, acc);

#pragma unroll
    for (int mi = 0; mi < 2; mi++)
#pragma unroll
        for (int f = 0; f < 8; f++) {
            const int r  = m0 + wm * 32 + mi * 16 + (l >> 2);
            const int cc = n0 + wn * 64 + f * 8 + ((l & 3) << 1);
            const float2 b2 = *(const float2*)&bo[cc];
            float2 v0, v1;
            v0.x = acc[mi][f][0] + b2.x; v0.y = acc[mi][f][1] + b2.y;
            v1.x = acc[mi][f][2] + b2.x; v1.y = acc[mi][f][3] + b2.y;
            *(float2*)&out[(size_t)r * DIM + cc] = v0;
            *(float2*)&out[(size_t)(r + 8) * DIM + cc] = v1;
        }
}

// ================== HMMA flash attention (causal, fp16) ====================
// 256 threads = 8 warps; warp w owns q-rows [w*16, w*16+16). BN=64 per iter.
// Double-buffered cp.async K/V, single __syncthreads per iteration.
#define QP 72                        // smem pitch (halfs): 144B rows
#define A_QBYTES (128 * QP * 2)      // 18432
#define A_KVBYTES (64 * QP * 2)      // 9216
#define A_KOFF(s) (A_QBYTES + (s) * A_KVBYTES)
#define A_VOFF(s) (A_QBYTES + 2 * A_KVBYTES + (s) * A_KVBYTES)
#define ATTN_SMEM_TOT (A_QBYTES + 4 * A_KVBYTES)   // 55296

__device__ __forceinline__ void attn_load_kv(
    char* smem, const __half* __restrict__ Kg, const __half* __restrict__ Vg,
    int j, int tid)
{
    const int s = j & 1;
    const uint32_t kB = smem_u32(smem + A_KOFF(s));
    const uint32_t vB = smem_u32(smem + A_VOFF(s));
#pragma unroll
    for (int i = 0; i < 2; i++) {
        int idx = i * 256 + tid;      // 0..511 chunks of 16B
        int r = idx >> 3, q = idx & 7;
        CP16(kB + r * (QP * 2) + q * 16, Kg + ((size_t)j * 64 + r) * HD + q * 8);
        CP16(vB + r * (QP * 2) + q * 16, Vg + ((size_t)j * 64 + r) * HD + q * 8);
    }
}

__global__ __launch_bounds__(256, 2) void attn_kernel()
{
    extern __shared__ char smem[];
    const int tid = threadIdx.x;
    const int l = tid & 31, wid = tid >> 5;
    const int qb = (gridDim.x - 1) - blockIdx.x;   // big blocks first
    const int h = blockIdx.y;

    const __half* Qg = g_qh + ((size_t)h * SEQ + (size_t)qb * 128) * HD;
    const __half* Kg = g_kh + (size_t)h * SEQ * HD;
    const __half* Vg = g_vh + (size_t)h * SEQ * HD;

    // kick off K/V tile 0 before staging Q
    attn_load_kv(smem, Kg, Vg, 0, tid);
    CP_COMMIT();

    // stage Q tile [128][64] -> pitch-72 smem
    __half* sQ = (__half*)smem;
#pragma unroll
    for (int i = 0; i < 4; i++) {
        int idx = i * 256 + tid;          // 0..1023 chunks of 16B
        int r = idx >> 3, q = idx & 7;
        *(uint4*)(sQ + r * QP + q * 8) = *(const uint4*)(Qg + (size_t)r * HD + q * 8);
    }
    __syncthreads();

    // Q fragments (A operand), rows warp*16..+15, k=64 in 4 k16 steps
    const uint32_t qB = smem_u32(smem);
    uint32_t qf[4][4];
    {
        const int row = wid * 16 + (l & 15);
        const int col = (l >> 4) << 3;
#pragma unroll
        for (int ks = 0; ks < 4; ks++)
            ldsm4(qf[ks], qB + (row * QP + ks * 16 + col) * 2);
    }

    const int r0g = qb * 128 + wid * 16 + (l >> 2);   // global q row (part 0)
    const int r1g = r0g + 8;                          // part 1
    float m0r = -1e30f, m1r = -1e30f, l0r = 0.f, l1r = 0.f;
    float oacc[8][4];
#pragma unroll
    for (int f = 0; f < 8; f++)
#pragma unroll
        for (int e = 0; e < 4; e++) oacc[f][e] = 0.f;

    // lane offsets for K (non-trans B frags) and V (trans B frags)
    const int kRow = (l & 7) + ((l >> 4) << 3);
    const int kCol = ((l >> 3) & 1) << 3;
    const int vRow = (l & 7) + (((l >> 3) & 1) << 3);
    const int vCol = (l >> 4) << 3;

    const int jmax = 2 * qb + 1;
    for (int j = 0; j <= jmax; j++) {
        CP_WAIT_G0();
        __syncthreads();
        if (j + 1 <= jmax) attn_load_kv(smem, Kg, Vg, j + 1, tid);
        CP_COMMIT();

        const uint32_t kB = smem_u32(smem + A_KOFF(j & 1));
        const uint32_t vB = smem_u32(smem + A_VOFF(j & 1));

        // ---- S = Q @ K^T : 16x64 per warp ----
        float sacc[8][4];
#pragma unroll
        for (int f = 0; f < 8; f++)
#pragma unroll
            for (int e = 0; e < 4; e++) sacc[f][e] = 0.f;

#pragma unroll
        for (int ks = 0; ks < 4; ks++) {
            uint32_t bf[4][4];
#pragma unroll
            for (int g = 0; g < 4; g++)
                ldsm4(bf[g], kB + ((g * 16 + kRow) * QP + ks * 16 + kCol) * 2);
#pragma unroll
            for (int f = 0; f < 8; f++) {
                const int g = f >> 1, o = (f & 1) * 2;
                mma16816(sacc[f], qf[ks], bf[g][o], bf[g][o + 1]);
            }
        }

        // ---- online softmax (thread-local rows r0g, r1g) ----
        const bool edge = (j >= 2 * qb);
        float mx0 = m0r, mx1 = m1r;
#pragma unroll
        for (int f = 0; f < 8; f++) {
            const int cb = j * 64 + f * 8 + ((l & 3) << 1);
            float v0 = sacc[f][0] * 0.125f, v1 = sacc[f][1] * 0.125f;
            float v2 = sacc[f][2] * 0.125f, v3 = sacc[f][3] * 0.125f;
            if (edge) {
                if (cb     > r0g) v0 = -1e30f;
                if (cb + 1 > r0g) v1 = -1e30f;
                if (cb     > r1g) v2 = -1e30f;
                if (cb + 1 > r1g) v3 = -1e30f;
            }
            sacc[f][0] = v0; sacc[f][1] = v1; sacc[f][2] = v2; sacc[f][3] = v3;
            mx0 = fmaxf(mx0, fmaxf(v0, v1));
            mx1 = fmaxf(mx1, fmaxf(v2, v3));
        }
        mx0 = fmaxf(mx0, __shfl_xor_sync(0xffffffffu, mx0, 1));
        mx0 = fmaxf(mx0, __shfl_xor_sync(0xffffffffu, mx0, 2));
        mx1 = fmaxf(mx1, __shfl_xor_sync(0xffffffffu, mx1, 1));
        mx1 = fmaxf(mx1, __shfl_xor_sync(0xffffffffu, mx1, 2));

        const float al0 = __expf(m0r - mx0);
        const float al1 = __expf(m1r - mx1);
        m0r = mx0; m1r = mx1;

        float s0 = 0.f, s1 = 0.f;
        uint32_t pl[8], ph[8];
#pragma unroll
        for (int f = 0; f < 8; f++) {
            const float p0 = __expf(sacc[f][0] - mx0);
            const float p1 = __expf(sacc[f][1] - mx0);
            const float p2 = __expf(sacc[f][2] - mx1);
            const float p3 = __expf(sacc[f][3] - mx1);
            s0 += p0 + p1; s1 += p2 + p3;
            pl[f] = pack_h2(p0, p1);
            ph[f] = pack_h2(p2, p3);
        }
        s0 += __shfl_xor_sync(0xffffffffu, s0, 1);
        s0 += __shfl_xor_sync(0xffffffffu, s0, 2);
        s1 += __shfl_xor_sync(0xffffffffu, s1, 1);
        s1 += __shfl_xor_sync(0xffffffffu, s1, 2);
        l0r = l0r * al0 + s0;
        l1r = l1r * al1 + s1;

        // ---- O = O*alpha + P @ V ----
#pragma unroll
        for (int f = 0; f < 8; f++) {
            oacc[f][0] *= al0; oacc[f][1] *= al0;
            oacc[f][2] *= al1; oacc[f][3] *= al1;
        }
#pragma unroll
        for (int ks = 0; ks < 4; ks++) {
            uint32_t a[4] = {pl[2 * ks], ph[2 * ks], pl[2 * ks + 1], ph[2 * ks + 1]};
            uint32_t bv[4][4];
#pragma unroll
            for (int g = 0; g < 4; g++)
                ldsm4t(bv[g], vB + ((ks * 16 + vRow) * QP + g * 16 + vCol) * 2);
#pragma unroll
            for (int f = 0; f < 8; f++) {
                const int g = f >> 1, o = (f & 1) * 2;
                mma16816(oacc[f], a, bv[g][o], bv[g][o + 1]);
            }
        }
    }

    // epilogue: ctx[row][h*64 + c] = O / l  (fp16)
    const float inv0 = 1.f / l0r, inv1 = 1.f / l1r;
#pragma unroll
    for (int f = 0; f < 8; f++) {
        const int cc = h * HD + f * 8 + ((l & 3) << 1);
        *(__half2*)&g_ctxh[(size_t)r0g * DIM + cc] =
            __floats2half2_rn(oacc[f][0] * inv0, oacc[f][1] * inv0);
        *(__half2*)&g_ctxh[(size_t)r1g * DIM + cc] =
            __floats2half2_rn(oacc[f][2] * inv1, oacc[f][3] * inv1);
    }
}

// ================================ launch ===================================
extern "C" void kernel_launch(void* const* d_in, const int* in_sizes, int n_in,
                              void* d_out, int out_size)
{
    (void)in_sizes; (void)n_in; (void)out_size;
    const float* x  = (const float*)d_in[0];
    const float* Wq = (const float*)d_in[1];
    const float* Wk = (const float*)d_in[2];
    const float* Wv = (const float*)d_in[3];
    const float* Wo = (const float*)d_in[4];
    const float* bo = (const float*)d_in[5];
    float* out = (float*)d_out;

    convert_kernel<<<8192, 256>>>(x, Wq, Wk, Wv, Wo);

    cudaFuncSetAttribute(gemm_proj_kernel,
                         cudaFuncAttributeMaxDynamicSharedMemorySize, GEMM_SMEM_TOT);
    gemm_proj_kernel<<<dim3(DIM / 128, SEQ / 128, 3), 256, GEMM_SMEM_TOT>>>();

    cudaFuncSetAttribute(attn_kernel,
                         cudaFuncAttributeMaxDynamicSharedMemorySize, ATTN_SMEM_TOT);
    attn_kernel<<<dim3(SEQ / 128, NH), 256, ATTN_SMEM_TOT>>>();

    cudaFuncSetAttribute(out_proj_kernel,
                         cudaFuncAttributeMaxDynamicSharedMemorySize, GEMM_SMEM_TOT);
    out_proj_kernel<<<dim3(DIM / 128, SEQ / 128), 256, GEMM_SMEM_TOT>>>(bo, out);
}

// round 12
// speedup vs baseline: 7.0640x; 1.0019x over previous
#include <cuda_runtime.h>
#include <cuda_fp16.h>
#include <stdint.h>

#define SEQ 4096
#define DIM 1024
#define NH  16
#define HD  64

// ---------------- fp16 scratch (device globals; no allocation allowed) -----
__device__ __align__(128) __half g_xh [SEQ * DIM];
__device__ __align__(128) __half g_wqh[DIM * DIM];
__device__ __align__(128) __half g_wkh[DIM * DIM];
__device__ __align__(128) __half g_wvh[DIM * DIM];
__device__ __align__(128) __half g_woh[DIM * DIM];
__device__ __align__(128) __half g_qh [NH * SEQ * HD];   // [h][s][hd]
__device__ __align__(128) __half g_kh [NH * SEQ * HD];   // [h][s][hd]
__device__ __align__(128) __half g_vh [NH * SEQ * HD];   // [h][s][hd]
__device__ __align__(128) __half g_ctxh[SEQ * DIM];      // [s][d]

// ========================= PTX helpers =====================================
__device__ __forceinline__ uint32_t smem_u32(const void* p) {
    uint32_t a;
    asm("{ .reg .u64 t; cvta.to.shared.u64 t, %1; cvt.u32.u64 %0, t; }"
        : "=r"(a) : "l"(p));
    return a;
}
__device__ __forceinline__ void ldsm4(uint32_t* r, uint32_t a) {
    asm volatile("ldmatrix.sync.aligned.m8n8.x4.shared.b16 {%0,%1,%2,%3}, [%4];"
                 : "=r"(r[0]), "=r"(r[1]), "=r"(r[2]), "=r"(r[3]) : "r"(a));
}
__device__ __forceinline__ void ldsm4t(uint32_t* r, uint32_t a) {
    asm volatile("ldmatrix.sync.aligned.m8n8.x4.trans.shared.b16 {%0,%1,%2,%3}, [%4];"
                 : "=r"(r[0]), "=r"(r[1]), "=r"(r[2]), "=r"(r[3]) : "r"(a));
}
__device__ __forceinline__ void mma16816(float* d, const uint32_t* a,
                                         uint32_t b0, uint32_t b1) {
    asm volatile(
        "mma.sync.aligned.m16n8k16.row.col.f32.f16.f16.f32 "
        "{%0,%1,%2,%3}, {%4,%5,%6,%7}, {%8,%9}, {%0,%1,%2,%3};"
        : "+f"(d[0]), "+f"(d[1]), "+f"(d[2]), "+f"(d[3])
        : "r"(a[0]), "r"(a[1]), "r"(a[2]), "r"(a[3]), "r"(b0), "r"(b1));
}
#define CP16(sa, gp) \
    asm volatile("cp.async.cg.shared.global [%0], [%1], 16;" :: "r"(sa), "l"(gp))
#define CP_COMMIT()  asm volatile("cp.async.commit_group;" ::: "memory")
#define CP_WAIT_G2() asm volatile("cp.async.wait_group 2;" ::: "memory")
#define CP_WAIT_G0() asm volatile("cp.async.wait_group 0;" ::: "memory")

__device__ __forceinline__ uint32_t pack_h2(float a, float b) {
    __half2 h = __floats2half2_rn(a, b);
    return *(uint32_t*)&h;
}

// =========================== fp32 -> fp16 convert ==========================
__global__ __launch_bounds__(256) void convert_kernel(
    const float* __restrict__ x,  const float* __restrict__ wq,
    const float* __restrict__ wk, const float* __restrict__ wv,
    const float* __restrict__ wo)
{
    const int i = blockIdx.x * 256 + threadIdx.x;   // float4 index
    const int XN = SEQ * DIM / 4, WN = DIM * DIM / 4;
    const float* src; __half* dst; int off;
    if (i < XN) { src = x; dst = g_xh; off = i; }
    else {
        int j = i - XN; int w = j / WN; off = j - w * WN;
        src = (w == 0) ? wq : (w == 1) ? wk : (w == 2) ? wv : wo;
        dst = (w == 0) ? g_wqh : (w == 1) ? g_wkh : (w == 2) ? g_wvh : g_woh;
    }
    float4 v = ((const float4*)src)[off];
    uint2 u;
    u.x = pack_h2(v.x, v.y);
    u.y = pack_h2(v.z, v.w);
    ((uint2*)dst)[off] = u;
}

// ================== HMMA GEMM: Y[m][n] = sum_k A[m][k] B[n][k] =============
// BM=128, BN=64, BK=32, 256 threads = 8 warps (4m x 2n), 32x32 per-warp tile.
// 4-stage cp.async pipeline, single __syncthreads per K-step, 3 CTAs/SM.
#define BK 32
#define AP 40                        // smem pitch in halfs (80B rows)
#define G_ABYTES (128 * AP * 2)      // 10240 B per stage (A, 128 rows)
#define G_BBYTES (64 * AP * 2)       // 5120 B per stage (B, 64 rows)
#define G_STAGE  (G_ABYTES + G_BBYTES)      // 15360 B
#define G_NSTAGE 4
#define GEMM_SMEM_TOT (G_NSTAGE * G_STAGE)  // 61440 B
#define G_NC (DIM / BK)              // 32

__device__ __forceinline__ void hgemm_load(
    char* smem, const __half* __restrict__ Ag, const __half* __restrict__ Bg,
    int c, int tid)
{
    const uint32_t base = smem_u32(smem + (c & (G_NSTAGE - 1)) * G_STAGE);
    // A: 128 rows x 4 chunks = 512
#pragma unroll
    for (int i = 0; i < 2; i++) {
        int idx = i * 256 + tid;
        int r = idx >> 2, q = idx & 3;
        CP16(base + r * (AP * 2) + q * 16, Ag + (size_t)r * DIM + c * BK + q * 8);
    }
    // B: 64 rows x 4 chunks = 256
    {
        int r = tid >> 2, q = tid & 3;
        CP16(base + G_ABYTES + r * (AP * 2) + q * 16,
             Bg + (size_t)r * DIM + c * BK + q * 8);
    }
}

__device__ __forceinline__ void hgemm_mainloop(
    char* smem, const __half* __restrict__ Ag, const __half* __restrict__ Bg,
    float acc[2][4][4])
{
    const int tid = threadIdx.x;
    const int l = tid & 31, wid = tid >> 5;
    const int wm = wid >> 1, wn = wid & 1;

#pragma unroll
    for (int mi = 0; mi < 2; mi++)
#pragma unroll
        for (int f = 0; f < 4; f++)
#pragma unroll
            for (int e = 0; e < 4; e++) acc[mi][f][e] = 0.f;

    // prologue: 3 stages in flight
#pragma unroll
    for (int s = 0; s < 3; s++) { hgemm_load(smem, Ag, Bg, s, tid); CP_COMMIT(); }

    // per-lane ldmatrix offsets (halfs)
    const int aRow = wm * 32 + (l & 15);
    const int aCol = (l >> 4) << 3;
    const int bRow = wn * 32 + (l & 7) + ((l >> 4) << 3);
    const int bCol = ((l >> 3) & 1) << 3;

    for (int c = 0; c < G_NC; c++) {
        CP_WAIT_G2();
        __syncthreads();
        if (c + 3 < G_NC) hgemm_load(smem, Ag, Bg, c + 3, tid);
        CP_COMMIT();   // unconditional: keeps wait_group accounting uniform

        const uint32_t aS = smem_u32(smem + (c & (G_NSTAGE - 1)) * G_STAGE);
        const uint32_t bS = aS + G_ABYTES;
#pragma unroll
        for (int ks = 0; ks < 2; ks++) {
            const int k0 = ks * 16;
            uint32_t af[2][4];
#pragma unroll
            for (int mi = 0; mi < 2; mi++)
                ldsm4(af[mi], aS + ((aRow + mi * 16) * AP + k0 + aCol) * 2);
            uint32_t bf[2][4];
#pragma unroll
            for (int g = 0; g < 2; g++)
                ldsm4(bf[g], bS + ((bRow + g * 16) * AP + k0 + bCol) * 2);
#pragma unroll
            for (int mi = 0; mi < 2; mi++)
#pragma unroll
                for (int f = 0; f < 4; f++) {
                    const int g = f >> 1, o = (f & 1) * 2;
                    mma16816(acc[mi][f], af[mi], bf[g][o], bf[g][o + 1]);
                }
        }
    }
}

__global__ __launch_bounds__(256, 3) void gemm_proj_kernel()
{
    extern __shared__ char smem[];
    const int tid = threadIdx.x;
    const int l = tid & 31, wid = tid >> 5;
    const int wm = wid >> 1, wn = wid & 1;
    const int m0 = blockIdx.y * 128, n0 = blockIdx.x * 64;
    const int z = blockIdx.z;
    const __half* B = (z == 0) ? g_wqh : (z == 1) ? g_wkh : g_wvh;
    __half* dst = (z == 0) ? g_qh : (z == 1) ? g_kh : g_vh;

    float acc[2][4][4];
    hgemm_mainloop(smem, g_xh + (size_t)m0 * DIM, B + (size_t)n0 * DIM, acc);

#pragma unroll
    for (int mi = 0; mi < 2; mi++)
#pragma unroll
        for (int f = 0; f < 4; f++) {
            const int r  = m0 + wm * 32 + mi * 16 + (l >> 2);
            const int cc = n0 + wn * 32 + f * 8 + ((l & 3) << 1);
            const int h = cc >> 6, hd = cc & 63;
            const size_t base = ((size_t)h * SEQ + r) * HD + hd;
            *(__half2*)&dst[base] = __floats2half2_rn(acc[mi][f][0], acc[mi][f][1]);
            *(__half2*)&dst[base + 8 * HD] =
                __floats2half2_rn(acc[mi][f][2], acc[mi][f][3]);
        }
}

__global__ __launch_bounds__(256, 3) void out_proj_kernel(
    const float* __restrict__ bo, float* __restrict__ out)
{
    extern __shared__ char smem[];
    const int tid = threadIdx.x;
    const int l = tid & 31, wid = tid >> 5;
    const int wm = wid >> 1, wn = wid & 1;
    const int m0 = blockIdx.y * 128, n0 = blockIdx.x * 64;

    float acc[2][4][4];
    hgemm_mainloop(smem, g_ctxh + (size_t)m0 * DIM, g_woh + (size_t)n0 * DIM, acc);

#pragma unroll
    for (int mi = 0; mi < 2; mi++)
#pragma unroll
        for (int f = 0; f < 4; f++) {
            const int r  = m0 + wm * 32 + mi * 16 + (l >> 2);
            const int cc = n0 + wn * 32 + f * 8 + ((l & 3) << 1);
            const float2 b2 = *(const float2*)&bo[cc];
            float2 v0, v1;
            v0.x = acc[mi][f][0] + b2.x; v0.y = acc[mi][f][1] + b2.y;
            v1.x = acc[mi][f][2] + b2.x; v1.y = acc[mi][f][3] + b2.y;
            *(float2*)&out[(size_t)r * DIM + cc] = v0;
            *(float2*)&out[(size_t)(r + 8) * DIM + cc] = v1;
        }
}

// ================== HMMA flash attention (causal, fp16) ====================
// 256 threads = 8 warps; warp w owns q-rows [w*16, w*16+16). BN=64 per iter.
// Double-buffered cp.async K/V, single __syncthreads per iteration.
#define QP 72                        // smem pitch (halfs): 144B rows
#define A_QBYTES (128 * QP * 2)      // 18432
#define A_KVBYTES (64 * QP * 2)      // 9216
#define A_KOFF(s) (A_QBYTES + (s) * A_KVBYTES)
#define A_VOFF(s) (A_QBYTES + 2 * A_KVBYTES + (s) * A_KVBYTES)
#define ATTN_SMEM_TOT (A_QBYTES + 4 * A_KVBYTES)   // 55296

__device__ __forceinline__ void attn_load_kv(
    char* smem, const __half* __restrict__ Kg, const __half* __restrict__ Vg,
    int j, int tid)
{
    const int s = j & 1;
    const uint32_t kB = smem_u32(smem + A_KOFF(s));
    const uint32_t vB = smem_u32(smem + A_VOFF(s));
#pragma unroll
    for (int i = 0; i < 2; i++) {
        int idx = i * 256 + tid;      // 0..511 chunks of 16B
        int r = idx >> 3, q = idx & 7;
        CP16(kB + r * (QP * 2) + q * 16, Kg + ((size_t)j * 64 + r) * HD + q * 8);
        CP16(vB + r * (QP * 2) + q * 16, Vg + ((size_t)j * 64 + r) * HD + q * 8);
    }
}

__global__ __launch_bounds__(256, 2) void attn_kernel()
{
    extern __shared__ char smem[];
    const int tid = threadIdx.x;
    const int l = tid & 31, wid = tid >> 5;
    const int qb = (gridDim.x - 1) - blockIdx.x;   // big blocks first
    const int h = blockIdx.y;

    const __half* Qg = g_qh + ((size_t)h * SEQ + (size_t)qb * 128) * HD;
    const __half* Kg = g_kh + (size_t)h * SEQ * HD;
    const __half* Vg = g_vh + (size_t)h * SEQ * HD;

    // kick off K/V tile 0 before staging Q
    attn_load_kv(smem, Kg, Vg, 0, tid);
    CP_COMMIT();

    // stage Q tile [128][64] -> pitch-72 smem
    __half* sQ = (__half*)smem;
#pragma unroll
    for (int i = 0; i < 4; i++) {
        int idx = i * 256 + tid;          // 0..1023 chunks of 16B
        int r = idx >> 3, q = idx & 7;
        *(uint4*)(sQ + r * QP + q * 8) = *(const uint4*)(Qg + (size_t)r * HD + q * 8);
    }
    __syncthreads();

    // Q fragments (A operand), rows warp*16..+15, k=64 in 4 k16 steps.
    // Fold the 1/sqrt(64)=0.125 softmax scale into Q once (exact in fp16).
    const uint32_t qB = smem_u32(smem);
    uint32_t qf[4][4];
    {
        const int row = wid * 16 + (l & 15);
        const int col = (l >> 4) << 3;
        const __half2 sc = __floats2half2_rn(0.125f, 0.125f);
#pragma unroll
        for (int ks = 0; ks < 4; ks++) {
            ldsm4(qf[ks], qB + (row * QP + ks * 16 + col) * 2);
#pragma unroll
            for (int e = 0; e < 4; e++) {
                __half2 v = __hmul2(*(__half2*)&qf[ks][e], sc);
                qf[ks][e] = *(uint32_t*)&v;
            }
        }
    }

    const int r0g = qb * 128 + wid * 16 + (l >> 2);   // global q row (part 0)
    const int r1g = r0g + 8;                          // part 1
    float m0r = -1e30f, m1r = -1e30f, l0r = 0.f, l1r = 0.f;
    float oacc[8][4];
#pragma unroll
    for (int f = 0; f < 8; f++)
#pragma unroll
        for (int e = 0; e < 4; e++) oacc[f][e] = 0.f;

    // lane offsets for K (non-trans B frags) and V (trans B frags)
    const int kRow = (l & 7) + ((l >> 4) << 3);
    const int kCol = ((l >> 3) & 1) << 3;
    const int vRow = (l & 7) + (((l >> 3) & 1) << 3);
    const int vCol = (l >> 4) << 3;

    const int jmax = 2 * qb + 1;
    for (int j = 0; j <= jmax; j++) {
        CP_WAIT_G0();
        __syncthreads();
        if (j + 1 <= jmax) attn_load_kv(smem, Kg, Vg, j + 1, tid);
        CP_COMMIT();

        const uint32_t kB = smem_u32(smem + A_KOFF(j & 1));
        const uint32_t vB = smem_u32(smem + A_VOFF(j & 1));

        // ---- S = (Q*0.125) @ K^T : 16x64 per warp ----
        float sacc[8][4];
#pragma unroll
        for (int f = 0; f < 8; f++)
#pragma unroll
            for (int e = 0; e < 4; e++) sacc[f][e] = 0.f;

#pragma unroll
        for (int ks = 0; ks < 4; ks++) {
            uint32_t bf[4][4];
#pragma unroll
            for (int g = 0; g < 4; g++)
                ldsm4(bf[g], kB + ((g * 16 + kRow) * QP + ks * 16 + kCol) * 2);
#pragma unroll
            for (int f = 0; f < 8; f++) {
                const int g = f >> 1, o = (f & 1) * 2;
                mma16816(sacc[f], qf[ks], bf[g][o], bf[g][o + 1]);
            }
        }

        // ---- online softmax (thread-local rows r0g, r1g) ----
        const bool edge = (j >= 2 * qb);
        float mx0 = m0r, mx1 = m1r;
#pragma unroll
        for (int f = 0; f < 8; f++) {
            const int cb = j * 64 + f * 8 + ((l & 3) << 1);
            float v0 = sacc[f][0], v1 = sacc[f][1];
            float v2 = sacc[f][2], v3 = sacc[f][3];
            if (edge) {
                if (cb     > r0g) v0 = -1e30f;
                if (cb + 1 > r0g) v1 = -1e30f;
                if (cb     > r1g) v2 = -1e30f;
                if (cb + 1 > r1g) v3 = -1e30f;
            }
            sacc[f][0] = v0; sacc[f][1] = v1; sacc[f][2] = v2; sacc[f][3] = v3;
            mx0 = fmaxf(mx0, fmaxf(v0, v1));
            mx1 = fmaxf(mx1, fmaxf(v2, v3));
        }
        mx0 = fmaxf(mx0, __shfl_xor_sync(0xffffffffu, mx0, 1));
        mx0 = fmaxf(mx0, __shfl_xor_sync(0xffffffffu, mx0, 2));
        mx1 = fmaxf(mx1, __shfl_xor_sync(0xffffffffu, mx1, 1));
        mx1 = fmaxf(mx1, __shfl_xor_sync(0xffffffffu, mx1, 2));

        const float al0 = __expf(m0r - mx0);
        const float al1 = __expf(m1r - mx1);
        m0r = mx0; m1r = mx1;

        float s0 = 0.f, s1 = 0.f;
        uint32_t pl[8], ph[8];
#pragma unroll
        for (int f = 0; f < 8; f++) {
            const float p0 = __expf(sacc[f][0] - mx0);
            const float p1 = __expf(sacc[f][1] - mx0);
            const float p2 = __expf(sacc[f][2] - mx1);
            const float p3 = __expf(sacc[f][3] - mx1);
            s0 += p0 + p1; s1 += p2 + p3;
            pl[f] = pack_h2(p0, p1);
            ph[f] = pack_h2(p2, p3);
        }
        s0 += __shfl_xor_sync(0xffffffffu, s0, 1);
        s0 += __shfl_xor_sync(0xffffffffu, s0, 2);
        s1 += __shfl_xor_sync(0xffffffffu, s1, 1);
        s1 += __shfl_xor_sync(0xffffffffu, s1, 2);
        l0r = l0r * al0 + s0;
        l1r = l1r * al1 + s1;

        // ---- O = O*alpha + P @ V ----
#pragma unroll
        for (int f = 0; f < 8; f++) {
            oacc[f][0] *= al0; oacc[f][1] *= al0;
            oacc[f][2] *= al1; oacc[f][3] *= al1;
        }
#pragma unroll
        for (int ks = 0; ks < 4; ks++) {
            uint32_t a[4] = {pl[2 * ks], ph[2 * ks], pl[2 * ks + 1], ph[2 * ks + 1]};
            uint32_t bv[4][4];
#pragma unroll
            for (int g = 0; g < 4; g++)
                ldsm4t(bv[g], vB + ((ks * 16 + vRow) * QP + g * 16 + vCol) * 2);
#pragma unroll
            for (int f = 0; f < 8; f++) {
                const int g = f >> 1, o = (f & 1) * 2;
                mma16816(oacc[f], a, bv[g][o], bv[g][o + 1]);
            }
        }
    }

    // epilogue: ctx[row][h*64 + c] = O / l  (fp16)
    const float inv0 = 1.f / l0r, inv1 = 1.f / l1r;
#pragma unroll
    for (int f = 0; f < 8; f++) {
        const int cc = h * HD + f * 8 + ((l & 3) << 1);
        *(__half2*)&g_ctxh[(size_t)r0g * DIM + cc] =
            __floats2half2_rn(oacc[f][0] * inv0, oacc[f][1] * inv0);
        *(__half2*)&g_ctxh[(size_t)r1g * DIM + cc] =
            __floats2half2_rn(oacc[f][2] * inv1, oacc[f][3] * inv1);
    }
}

// ================================ launch ===================================
extern "C" void kernel_launch(void* const* d_in, const int* in_sizes, int n_in,
                              void* d_out, int out_size)
{
    (void)in_sizes; (void)n_in; (void)out_size;
    const float* x  = (const float*)d_in[0];
    const float* Wq = (const float*)d_in[1];
    const float* Wk = (const float*)d_in[2];
    const float* Wv = (const float*)d_in[3];
    const float* Wo = (const float*)d_in[4];
    const float* bo = (const float*)d_in[5];
    float* out = (float*)d_out;

    convert_kernel<<<8192, 256>>>(x, Wq, Wk, Wv, Wo);

    cudaFuncSetAttribute(gemm_proj_kernel,
                         cudaFuncAttributeMaxDynamicSharedMemorySize, GEMM_SMEM_TOT);
    gemm_proj_kernel<<<dim3(DIM / 64, SEQ / 128, 3), 256, GEMM_SMEM_TOT>>>();

    cudaFuncSetAttribute(attn_kernel,
                         cudaFuncAttributeMaxDynamicSharedMemorySize, ATTN_SMEM_TOT);
    attn_kernel<<<dim3(SEQ / 128, NH), 256, ATTN_SMEM_TOT>>>();

    cudaFuncSetAttribute(out_proj_kernel,
                         cudaFuncAttributeMaxDynamicSharedMemorySize, GEMM_SMEM_TOT);
    out_proj_kernel<<<dim3(DIM / 64, SEQ / 128), 256, GEMM_SMEM_TOT>>>(bo, out);
}

// round 14
// speedup vs baseline: 7.6134x; 1.0778x over previous
#include <cuda_runtime.h>
#include <cuda_fp16.h>
#include <stdint.h>

#define SEQ 4096
#define DIM 1024
#define NH  16
#define HD  64

// ---------------- fp16 scratch (device globals; no allocation allowed) -----
__device__ __align__(128) __half g_xh [SEQ * DIM];
__device__ __align__(128) __half g_wqh[DIM * DIM];
__device__ __align__(128) __half g_wkh[DIM * DIM];
__device__ __align__(128) __half g_wvh[DIM * DIM];
__device__ __align__(128) __half g_woh[DIM * DIM];
__device__ __align__(128) __half g_qh [NH * SEQ * HD];   // [h][s][hd]
__device__ __align__(128) __half g_kh [NH * SEQ * HD];   // [h][s][hd]
__device__ __align__(128) __half g_vh [NH * SEQ * HD];   // [h][s][hd]
__device__ __align__(128) __half g_ctxh[SEQ * DIM];      // [s][d]

// ========================= PTX helpers =====================================
__device__ __forceinline__ uint32_t smem_u32(const void* p) {
    uint32_t a;
    asm("{ .reg .u64 t; cvta.to.shared.u64 t, %1; cvt.u32.u64 %0, t; }"
        : "=r"(a) : "l"(p));
    return a;
}
__device__ __forceinline__ void ldsm4(uint32_t* r, uint32_t a) {
    asm volatile("ldmatrix.sync.aligned.m8n8.x4.shared.b16 {%0,%1,%2,%3}, [%4];"
                 : "=r"(r[0]), "=r"(r[1]), "=r"(r[2]), "=r"(r[3]) : "r"(a));
}
__device__ __forceinline__ void ldsm4t(uint32_t* r, uint32_t a) {
    asm volatile("ldmatrix.sync.aligned.m8n8.x4.trans.shared.b16 {%0,%1,%2,%3}, [%4];"
                 : "=r"(r[0]), "=r"(r[1]), "=r"(r[2]), "=r"(r[3]) : "r"(a));
}
__device__ __forceinline__ void mma16816(float* d, const uint32_t* a,
                                         uint32_t b0, uint32_t b1) {
    asm volatile(
        "mma.sync.aligned.m16n8k16.row.col.f32.f16.f16.f32 "
        "{%0,%1,%2,%3}, {%4,%5,%6,%7}, {%8,%9}, {%0,%1,%2,%3};"
        : "+f"(d[0]), "+f"(d[1]), "+f"(d[2]), "+f"(d[3])
        : "r"(a[0]), "r"(a[1]), "r"(a[2]), "r"(a[3]), "r"(b0), "r"(b1));
}
__device__ __forceinline__ float ex2f(float x) {
    float y;
    asm("ex2.approx.f32 %0, %1;" : "=f"(y) : "f"(x));
    return y;
}
#define CP16(sa, gp) \
    asm volatile("cp.async.cg.shared.global [%0], [%1], 16;" :: "r"(sa), "l"(gp))
#define CP_COMMIT()  asm volatile("cp.async.commit_group;" ::: "memory")
#define CP_WAIT_G1() asm volatile("cp.async.wait_group 1;" ::: "memory")
#define CP_WAIT_G0() asm volatile("cp.async.wait_group 0;" ::: "memory")

__device__ __forceinline__ uint32_t pack_h2(float a, float b) {
    __half2 h = __floats2half2_rn(a, b);
    return *(uint32_t*)&h;
}

// =========================== fp32 -> fp16 convert ==========================
__global__ __launch_bounds__(256) void convert_kernel(
    const float* __restrict__ x,  const float* __restrict__ wq,
    const float* __restrict__ wk, const float* __restrict__ wv,
    const float* __restrict__ wo)
{
    const int i = blockIdx.x * 256 + threadIdx.x;   // float4 index
    const int XN = SEQ * DIM / 4, WN = DIM * DIM / 4;
    const float* src; __half* dst; int off;
    if (i < XN) { src = x; dst = g_xh; off = i; }
    else {
        int j = i - XN; int w = j / WN; off = j - w * WN;
        src = (w == 0) ? wq : (w == 1) ? wk : (w == 2) ? wv : wo;
        dst = (w == 0) ? g_wqh : (w == 1) ? g_wkh : (w == 2) ? g_wvh : g_woh;
    }
    float4 v = ((const float4*)src)[off];
    uint2 u;
    u.x = pack_h2(v.x, v.y);
    u.y = pack_h2(v.z, v.w);
    ((uint2*)dst)[off] = u;
}

// ================== HMMA GEMM: Y[m][n] = sum_k A[m][k] B[n][k] =============
// BM=BN=128, BK=64, 256 threads = 8 warps (4m x 2n), 32x64 per-warp tile.
// 3-stage cp.async pipeline, single __syncthreads per 64-wide K step.
#define BK 64
#define AP 72                        // smem pitch in halfs (144B rows)
#define G_ABYTES (128 * AP * 2)      // 18432 B per stage per operand
#define G_STAGE  (2 * G_ABYTES)      // 36864 B per stage (A + B)
#define G_NSTAGE 3
#define GEMM_SMEM_TOT (G_NSTAGE * G_STAGE)   // 110592 B
#define G_NC (DIM / BK)              // 16

__device__ __forceinline__ void hgemm_load(
    char* smem, const __half* __restrict__ Ag, const __half* __restrict__ Bg,
    int c, int tid)
{
    const uint32_t base = smem_u32(smem + (c % G_NSTAGE) * G_STAGE);
    // A and B: 128 rows x 8 chunks of 16B each = 1024 cp.async per operand
#pragma unroll
    for (int i = 0; i < 4; i++) {
        int idx = i * 256 + tid;
        int r = idx >> 3, q = idx & 7;
        CP16(base + r * (AP * 2) + q * 16, Ag + (size_t)r * DIM + c * BK + q * 8);
        CP16(base + G_ABYTES + r * (AP * 2) + q * 16,
             Bg + (size_t)r * DIM + c * BK + q * 8);
    }
}

__device__ __forceinline__ void hgemm_mainloop(
    char* smem, const __half* __restrict__ Ag, const __half* __restrict__ Bg,
    float acc[2][8][4])
{
    const int tid = threadIdx.x;
    const int l = tid & 31, wid = tid >> 5;
    const int wm = wid >> 1, wn = wid & 1;

#pragma unroll
    for (int mi = 0; mi < 2; mi++)
#pragma unroll
        for (int f = 0; f < 8; f++)
#pragma unroll
            for (int e = 0; e < 4; e++) acc[mi][f][e] = 0.f;

    // prologue: 2 stages in flight
#pragma unroll
    for (int s = 0; s < 2; s++) { hgemm_load(smem, Ag, Bg, s, tid); CP_COMMIT(); }

    // per-lane ldmatrix offsets (halfs)
    const int aRow = wm * 32 + (l & 15);
    const int aCol = (l >> 4) << 3;
    const int bRow = wn * 64 + (l & 7) + ((l >> 4) << 3);
    const int bCol = ((l >> 3) & 1) << 3;

    for (int c = 0; c < G_NC; c++) {
        CP_WAIT_G1();
        __syncthreads();
        if (c + 2 < G_NC) hgemm_load(smem, Ag, Bg, c + 2, tid);
        CP_COMMIT();   // unconditional: keeps wait_group accounting uniform

        const uint32_t aS = smem_u32(smem + (c % G_NSTAGE) * G_STAGE);
        const uint32_t bS = aS + G_ABYTES;
#pragma unroll
        for (int ks = 0; ks < 4; ks++) {
            const int k0 = ks * 16;
            uint32_t af[2][4];
#pragma unroll
            for (int mi = 0; mi < 2; mi++)
                ldsm4(af[mi], aS + ((aRow + mi * 16) * AP + k0 + aCol) * 2);
            uint32_t bf[4][4];
#pragma unroll
            for (int g = 0; g < 4; g++)
                ldsm4(bf[g], bS + ((bRow + g * 16) * AP + k0 + bCol) * 2);
#pragma unroll
            for (int mi = 0; mi < 2; mi++)
#pragma unroll
                for (int f = 0; f < 8; f++) {
                    const int g = f >> 1, o = (f & 1) * 2;
                    mma16816(acc[mi][f], af[mi], bf[g][o], bf[g][o + 1]);
                }
        }
    }
}

__global__ __launch_bounds__(256, 2) void gemm_proj_kernel()
{
    extern __shared__ char smem[];
    const int tid = threadIdx.x;
    const int l = tid & 31, wid = tid >> 5;
    const int wm = wid >> 1, wn = wid & 1;
    const int m0 = blockIdx.y * 128, n0 = blockIdx.x * 128;
    const int z = blockIdx.z;
    const __half* B = (z == 0) ? g_wqh : (z == 1) ? g_wkh : g_wvh;
    __half* dst = (z == 0) ? g_qh : (z == 1) ? g_kh : g_vh;

    float acc[2][8][4];
    hgemm_mainloop(smem, g_xh + (size_t)m0 * DIM, B + (size_t)n0 * DIM, acc);

#pragma unroll
    for (int mi = 0; mi < 2; mi++)
#pragma unroll
        for (int f = 0; f < 8; f++) {
            const int r  = m0 + wm * 32 + mi * 16 + (l >> 2);
            const int cc = n0 + wn * 64 + f * 8 + ((l & 3) << 1);
            const int h = cc >> 6, hd = cc & 63;
            const size_t base = ((size_t)h * SEQ + r) * HD + hd;
            *(__half2*)&dst[base] = __floats2half2_rn(acc[mi][f][0], acc[mi][f][1]);
            *(__half2*)&dst[base + 8 * HD] =
                __floats2half2_rn(acc[mi][f][2], acc[mi][f][3]);
        }
}

__global__ __launch_bounds__(256, 2) void out_proj_kernel(
    const float* __restrict__ bo, float* __restrict__ out)
{
    extern __shared__ char smem[];
    const int tid = threadIdx.x;
    const int l = tid & 31, wid = tid >> 5;
    const int wm = wid >> 1, wn = wid & 1;
    const int m0 = blockIdx.y * 128, n0 = blockIdx.x * 128;

    float acc[2][8][4];
    hgemm_mainloop(smem, g_ctxh + (size_t)m0 * DIM, g_woh + (size_t)n0 * DIM, acc);

#pragma unroll
    for (int mi = 0; mi < 2; mi++)
#pragma unroll
        for (int f = 0; f < 8; f++) {
            const int r  = m0 + wm * 32 + mi * 16 + (l >> 2);
            const int cc = n0 + wn * 64 + f * 8 + ((l & 3) << 1);
            const float2 b2 = *(const float2*)&bo[cc];
            float2 v0, v1;
            v0.x = acc[mi][f][0] + b2.x; v0.y = acc[mi][f][1] + b2.y;
            v1.x = acc[mi][f][2] + b2.x; v1.y = acc[mi][f][3] + b2.y;
            *(float2*)&out[(size_t)r * DIM + cc] = v0;
            *(float2*)&out[(size_t)(r + 8) * DIM + cc] = v1;
        }
}

// ================== HMMA flash attention (causal, fp16) ====================
// 256 threads = 8 warps; warp w owns q-rows [w*16, w*16+16). BN=64 per iter.
// Double-buffered cp.async K/V, single __syncthreads per iteration.
// Softmax runs in the exp2 domain: Q is pre-scaled by 0.125*log2(e), so
// p = ex2(s - m) is a single MUFU op and the normalization is unchanged.
#define QP 72                        // smem pitch (halfs): 144B rows
#define A_QBYTES (128 * QP * 2)      // 18432
#define A_KVBYTES (64 * QP * 2)      // 9216
#define A_KOFF(s) (A_QBYTES + (s) * A_KVBYTES)
#define A_VOFF(s) (A_QBYTES + 2 * A_KVBYTES + (s) * A_KVBYTES)
#define ATTN_SMEM_TOT (A_QBYTES + 4 * A_KVBYTES)   // 55296

__device__ __forceinline__ void attn_load_kv(
    char* smem, const __half* __restrict__ Kg, const __half* __restrict__ Vg,
    int j, int tid)
{
    const int s = j & 1;
    const uint32_t kB = smem_u32(smem + A_KOFF(s));
    const uint32_t vB = smem_u32(smem + A_VOFF(s));
#pragma unroll
    for (int i = 0; i < 2; i++) {
        int idx = i * 256 + tid;      // 0..511 chunks of 16B
        int r = idx >> 3, q = idx & 7;
        CP16(kB + r * (QP * 2) + q * 16, Kg + ((size_t)j * 64 + r) * HD + q * 8);
        CP16(vB + r * (QP * 2) + q * 16, Vg + ((size_t)j * 64 + r) * HD + q * 8);
    }
}

__global__ __launch_bounds__(256, 2) void attn_kernel()
{
    extern __shared__ char smem[];
    const int tid = threadIdx.x;
    const int l = tid & 31, wid = tid >> 5;
    const int qb = (gridDim.x - 1) - blockIdx.x;   // big blocks first
    const int h = blockIdx.y;

    const __half* Qg = g_qh + ((size_t)h * SEQ + (size_t)qb * 128) * HD;
    const __half* Kg = g_kh + (size_t)h * SEQ * HD;
    const __half* Vg = g_vh + (size_t)h * SEQ * HD;

    // kick off K/V tile 0 before staging Q
    attn_load_kv(smem, Kg, Vg, 0, tid);
    CP_COMMIT();

    // stage Q tile [128][64] -> pitch-72 smem
    __half* sQ = (__half*)smem;
#pragma unroll
    for (int i = 0; i < 4; i++) {
        int idx = i * 256 + tid;          // 0..1023 chunks of 16B
        int r = idx >> 3, q = idx & 7;
        *(uint4*)(sQ + r * QP + q * 8) = *(const uint4*)(Qg + (size_t)r * HD + q * 8);
    }
    __syncthreads();

    // Q fragments (A operand), rows warp*16..+15, k=64 in 4 k16 steps.
    // Fold 0.125 * log2(e) into Q: softmax then runs in the exp2 domain.
    const uint32_t qB = smem_u32(smem);
    uint32_t qf[4][4];
    {
        const int row = wid * 16 + (l & 15);
        const int col = (l >> 4) << 3;
        const float qs = 0.125f * 1.44269504f;
        const __half2 sc = __floats2half2_rn(qs, qs);
#pragma unroll
        for (int ks = 0; ks < 4; ks++) {
            ldsm4(qf[ks], qB + (row * QP + ks * 16 + col) * 2);
#pragma unroll
            for (int e = 0; e < 4; e++) {
                __half2 v = __hmul2(*(__half2*)&qf[ks][e], sc);
                qf[ks][e] = *(uint32_t*)&v;
            }
        }
    }

    const int r0g = qb * 128 + wid * 16 + (l >> 2);   // global q row (part 0)
    const int r1g = r0g + 8;                          // part 1
    float m0r = -1e30f, m1r = -1e30f, l0r = 0.f, l1r = 0.f;
    float oacc[8][4];
#pragma unroll
    for (int f = 0; f < 8; f++)
#pragma unroll
        for (int e = 0; e < 4; e++) oacc[f][e] = 0.f;

    // lane offsets for K (non-trans B frags) and V (trans B frags)
    const int kRow = (l & 7) + ((l >> 4) << 3);
    const int kCol = ((l >> 3) & 1) << 3;
    const int vRow = (l & 7) + (((l >> 3) & 1) << 3);
    const int vCol = (l >> 4) << 3;

    const int jmax = 2 * qb + 1;
    for (int j = 0; j <= jmax; j++) {
        CP_WAIT_G0();
        __syncthreads();
        if (j + 1 <= jmax) attn_load_kv(smem, Kg, Vg, j + 1, tid);
        CP_COMMIT();

        const uint32_t kB = smem_u32(smem + A_KOFF(j & 1));
        const uint32_t vB = smem_u32(smem + A_VOFF(j & 1));

        // ---- S = (Q*qs) @ K^T : 16x64 per warp (log2-domain scores) ----
        float sacc[8][4];
#pragma unroll
        for (int f = 0; f < 8; f++)
#pragma unroll
            for (int e = 0; e < 4; e++) sacc[f][e] = 0.f;

#pragma unroll
        for (int ks = 0; ks < 4; ks++) {
            uint32_t bf[4][4];
#pragma unroll
            for (int g = 0; g < 4; g++)
                ldsm4(bf[g], kB + ((g * 16 + kRow) * QP + ks * 16 + kCol) * 2);
#pragma unroll
            for (int f = 0; f < 8; f++) {
                const int g = f >> 1, o = (f & 1) * 2;
                mma16816(sacc[f], qf[ks], bf[g][o], bf[g][o + 1]);
            }
        }

        // ---- online softmax (thread-local rows r0g, r1g), exp2 domain ----
        const bool edge = (j >= 2 * qb);
        float mx0 = m0r, mx1 = m1r;
#pragma unroll
        for (int f = 0; f < 8; f++) {
            const int cb = j * 64 + f * 8 + ((l & 3) << 1);
            float v0 = sacc[f][0], v1 = sacc[f][1];
            float v2 = sacc[f][2], v3 = sacc[f][3];
            if (edge) {
                if (cb     > r0g) v0 = -1e30f;
                if (cb + 1 > r0g) v1 = -1e30f;
                if (cb     > r1g) v2 = -1e30f;
                if (cb + 1 > r1g) v3 = -1e30f;
            }
            sacc[f][0] = v0; sacc[f][1] = v1; sacc[f][2] = v2; sacc[f][3] = v3;
            mx0 = fmaxf(mx0, fmaxf(v0, v1));
            mx1 = fmaxf(mx1, fmaxf(v2, v3));
        }
        mx0 = fmaxf(mx0, __shfl_xor_sync(0xffffffffu, mx0, 1));
        mx0 = fmaxf(mx0, __shfl_xor_sync(0xffffffffu, mx0, 2));
        mx1 = fmaxf(mx1, __shfl_xor_sync(0xffffffffu, mx1, 1));
        mx1 = fmaxf(mx1, __shfl_xor_sync(0xffffffffu, mx1, 2));

        const float al0 = ex2f(m0r - mx0);
        const float al1 = ex2f(m1r - mx1);
        m0r = mx0; m1r = mx1;

        float s0 = 0.f, s1 = 0.f;
        uint32_t pl[8], ph[8];
#pragma unroll
        for (int f = 0; f < 8; f++) {
            const float p0 = ex2f(sacc[f][0] - mx0);
            const float p1 = ex2f(sacc[f][1] - mx0);
            const float p2 = ex2f(sacc[f][2] - mx1);
            const float p3 = ex2f(sacc[f][3] - mx1);
            s0 += p0 + p1; s1 += p2 + p3;
            pl[f] = pack_h2(p0, p1);
            ph[f] = pack_h2(p2, p3);
        }
        s0 += __shfl_xor_sync(0xffffffffu, s0, 1);
        s0 += __shfl_xor_sync(0xffffffffu, s0, 2);
        s1 += __shfl_xor_sync(0xffffffffu, s1, 1);
        s1 += __shfl_xor_sync(0xffffffffu, s1, 2);
        l0r = l0r * al0 + s0;
        l1r = l1r * al1 + s1;

        // ---- O = O*alpha + P @ V ----
#pragma unroll
        for (int f = 0; f < 8; f++) {
            oacc[f][0] *= al0; oacc[f][1] *= al0;
            oacc[f][2] *= al1; oacc[f][3] *= al1;
        }
#pragma unroll
        for (int ks = 0; ks < 4; ks++) {
            uint32_t a[4] = {pl[2 * ks], ph[2 * ks], pl[2 * ks + 1], ph[2 * ks + 1]};
            uint32_t bv[4][4];
#pragma unroll
            for (int g = 0; g < 4; g++)
                ldsm4t(bv[g], vB + ((ks * 16 + vRow) * QP + g * 16 + vCol) * 2);
#pragma unroll
            for (int f = 0; f < 8; f++) {
                const int g = f >> 1, o = (f & 1) * 2;
                mma16816(oacc[f], a, bv[g][o], bv[g][o + 1]);
            }
        }
    }

    // epilogue: ctx[row][h*64 + c] = O / l  (fp16)
    const float inv0 = 1.f / l0r, inv1 = 1.f / l1r;
#pragma unroll
    for (int f = 0; f < 8; f++) {
        const int cc = h * HD + f * 8 + ((l & 3) << 1);
        *(__half2*)&g_ctxh[(size_t)r0g * DIM + cc] =
            __floats2half2_rn(oacc[f][0] * inv0, oacc[f][1] * inv0);
        *(__half2*)&g_ctxh[(size_t)r1g * DIM + cc] =
            __floats2half2_rn(oacc[f][2] * inv1, oacc[f][3] * inv1);
    }
}

// ================================ launch ===================================
extern "C" void kernel_launch(void* const* d_in, const int* in_sizes, int n_in,
                              void* d_out, int out_size)
{
    (void)in_sizes; (void)n_in; (void)out_size;
    const float* x  = (const float*)d_in[0];
    const float* Wq = (const float*)d_in[1];
    const float* Wk = (const float*)d_in[2];
    const float* Wv = (const float*)d_in[3];
    const float* Wo = (const float*)d_in[4];
    const float* bo = (const float*)d_in[5];
    float* out = (float*)d_out;

    convert_kernel<<<8192, 256>>>(x, Wq, Wk, Wv, Wo);

    cudaFuncSetAttribute(gemm_proj_kernel,
                         cudaFuncAttributeMaxDynamicSharedMemorySize, GEMM_SMEM_TOT);
    gemm_proj_kernel<<<dim3(DIM / 128, SEQ / 128, 3), 256, GEMM_SMEM_TOT>>>();

    cudaFuncSetAttribute(attn_kernel,
                         cudaFuncAttributeMaxDynamicSharedMemorySize, ATTN_SMEM_TOT);
    attn_kernel<<<dim3(SEQ / 128, NH), 256, ATTN_SMEM_TOT>>>();

    cudaFuncSetAttribute(out_proj_kernel,
                         cudaFuncAttributeMaxDynamicSharedMemorySize, GEMM_SMEM_TOT);
    out_proj_kernel<<<dim3(DIM / 128, SEQ / 128), 256, GEMM_SMEM_TOT>>>(bo, out);
}